// round 8
// baseline (speedup 1.0000x reference)
#include <cuda_runtime.h>
#include <cuda_fp16.h>
#include <math.h>
#include <stdint.h>

// Problem constants
#define BB 2
#define TT 2048
#define DD 2048
#define HH 16
#define DKq 64
#define DVv 128
#define RR 16
#define CC 64
#define NCC 32
#define MM (BB*TT)          // 4096
#define NQK (HH*DKq)        // 1024
#define NV  (HH*DVv)        // 2048
#define GLN_INV (1.0f/16.0f)
#define EPSL 1e-5f

// ---------------- scratch (device globals, no allocs allowed) ----------------
__device__ float g_q [MM*NQK];
__device__ float g_k [MM*NQK];
__device__ float g_v [MM*NV];
__device__ float g_gk[MM*NQK];
__device__ float g_r1[MM*RR];
__device__ float g_r2[MM*RR];
__device__ float g_g [MM*NV];
__device__ float g_o [MM*NV];
__device__ __half g_hsh[MM*DD];     // fp16 hs
__device__ __half g_wqh[DD*NQK];    // fp16 transposed weights [N][K]
__device__ __half g_wkh[DD*NQK];
__device__ __half g_wvh[DD*NV];
__device__ __half g_woh[NV*DD];
__device__ __half g_oh [MM*NV];     // fp16 gated o for final GEMM

// ---------------- helpers ----------------
__device__ __forceinline__ void cp16(void* smem_dst, const void* gmem_src) {
    uint32_t s = (uint32_t)__cvta_generic_to_shared(smem_dst);
    asm volatile("cp.async.cg.shared.global [%0], [%1], 16;" :: "r"(s), "l"(gmem_src));
}

// fp32 -> fp16 convert (copy)
__global__ __launch_bounds__(256) void to_half_kernel(
    const float* __restrict__ src, __half* __restrict__ dst, int n4)
{
    int i = blockIdx.x * 256 + threadIdx.x;
    if (i < n4) {
        float4 v = ((const float4*)src)[i];
        __half2 h0 = __floats2half2_rn(v.x, v.y);
        __half2 h1 = __floats2half2_rn(v.z, v.w);
        uint2 o;
        o.x = *(uint32_t*)&h0;
        o.y = *(uint32_t*)&h1;
        *(uint2*)(dst + (long)i * 4) = o;
    }
}

// transpose + convert: W[K][N] fp32 -> WT[N][K] fp16
__global__ __launch_bounds__(256) void transpose_half_kernel(
    const float* __restrict__ W, __half* __restrict__ WT, int K, int N)
{
    __shared__ float t[32][33];
    const int tx = threadIdx.x;       // 0..31
    const int ty = threadIdx.y;       // 0..7
    const int n0 = blockIdx.x * 32;
    const int k0 = blockIdx.y * 32;
#pragma unroll
    for (int i = 0; i < 4; i++)
        t[ty + 8*i][tx] = W[(long)(k0 + ty + 8*i) * N + n0 + tx];
    __syncthreads();
#pragma unroll
    for (int i = 0; i < 4; i++)
        WT[(long)(n0 + ty + 8*i) * K + k0 + tx] = __float2half_rn(t[tx][ty + 8*i]);
}

// ---------------- fp16 mma.sync GEMM: C = act(A[M,K] @ BT[N,K]^T) ------------
// BM=128, BN=256, BK=32 (halves). 512 threads (16 warps), warp tile 32x64,
// mma m16n8k16, 4-stage cp.async ring. Smem rows padded to 40 halves (80B):
// fragment word addr = 20*g + tig (+c) -> all 32 banks distinct, conflict-free.
#define HSTRIDE 40
#define HS_A (128*HSTRIDE)                // 5120 halves
#define HS_B (256*HSTRIDE)                // 10240 halves
#define STAGE_H (HS_A + HS_B)             // 15360 halves = 30720 B
#define HSTAGES 4
#define HSM_BYTES (HSTAGES*STAGE_H*2)     // 122880

template<bool SILU>
__global__ __launch_bounds__(512, 1) void h16gemm_kernel(
    const __half* __restrict__ A,
    const __half* __restrict__ BTa, const __half* __restrict__ BTb,
    float* __restrict__ Ca, float* __restrict__ Cb,
    int M, int N, int K)
{
    extern __shared__ __half smh[];
    const __half* BT = blockIdx.z ? BTb : BTa;
    float* C = blockIdx.z ? Cb : Ca;

    const int tid  = threadIdx.x;
    const int warp = tid >> 5;
    const int lane = tid & 31;
    const int g    = lane >> 2;          // 0..7
    const int tig  = lane & 3;           // 0..3
    const int wm   = (warp >> 2) * 32;   // 0,32,64,96
    const int wn   = (warp & 3) * 64;    // 0,64,128,192
    const int bm   = blockIdx.y * 128;
    const int bn   = blockIdx.x * 256;
    const int NIT  = K >> 5;

    float c[2][8][4];
#pragma unroll
    for (int mt = 0; mt < 2; mt++)
#pragma unroll
        for (int nt = 0; nt < 8; nt++)
#pragma unroll
            for (int r = 0; r < 4; r++) c[mt][nt][r] = 0.f;

    auto fill = [&](int t) {
        __half* As = smh + (t & 3) * STAGE_H;
        __half* Bs = As + HS_A;
        const int kbase = t << 5;
        // A tile: 128 rows x 32 halves = 512 16B chunks, 1 per thread
        {
            int row = tid >> 2;
            int c4  = tid & 3;
            cp16(As + row * HSTRIDE + c4 * 8,
                 A + (long)(bm + row) * K + kbase + c4 * 8);
        }
        // B tile: 256 rows x 32 halves = 1024 chunks, 2 per thread
#pragma unroll
        for (int i = 0; i < 2; i++) {
            int idx = tid + i * 512;
            int row = idx >> 2;
            int c4  = idx & 3;
            cp16(Bs + row * HSTRIDE + c4 * 8,
                 BT + (long)(bn + row) * K + kbase + c4 * 8);
        }
        asm volatile("cp.async.commit_group;");
    };

    fill(0); fill(1); fill(2);

    for (int t = 0; t < NIT; t++) {
        int rem = NIT - 1 - t;
        if (rem >= 2)      asm volatile("cp.async.wait_group 2;");
        else if (rem == 1) asm volatile("cp.async.wait_group 1;");
        else               asm volatile("cp.async.wait_group 0;");
        __syncthreads();

        const __half* As = smh + (t & 3) * STAGE_H;
        const __half* Bs = As + HS_A;

#pragma unroll
        for (int ks = 0; ks < 2; ks++) {
            uint32_t a[2][4];
#pragma unroll
            for (int mt = 0; mt < 2; mt++) {
                const __half* ap = As + (wm + mt * 16 + g) * HSTRIDE + ks * 16 + 2 * tig;
                a[mt][0] = *(const uint32_t*)(ap);                  // row g,   k+0
                a[mt][1] = *(const uint32_t*)(ap + 8 * HSTRIDE);    // row g+8, k+0
                a[mt][2] = *(const uint32_t*)(ap + 8);              // row g,   k+8
                a[mt][3] = *(const uint32_t*)(ap + 8 * HSTRIDE + 8);// row g+8, k+8
            }
            uint32_t b[8][2];
#pragma unroll
            for (int nt = 0; nt < 8; nt++) {
                const __half* bp = Bs + (wn + nt * 8 + g) * HSTRIDE + ks * 16 + 2 * tig;
                b[nt][0] = *(const uint32_t*)(bp);
                b[nt][1] = *(const uint32_t*)(bp + 8);
            }
#pragma unroll
            for (int mt = 0; mt < 2; mt++)
#pragma unroll
                for (int nt = 0; nt < 8; nt++) {
                    asm volatile(
                        "mma.sync.aligned.m16n8k16.row.col.f32.f16.f16.f32 "
                        "{%0,%1,%2,%3}, {%4,%5,%6,%7}, {%8,%9}, {%0,%1,%2,%3};"
                        : "+f"(c[mt][nt][0]), "+f"(c[mt][nt][1]),
                          "+f"(c[mt][nt][2]), "+f"(c[mt][nt][3])
                        : "r"(a[mt][0]), "r"(a[mt][1]), "r"(a[mt][2]), "r"(a[mt][3]),
                          "r"(b[nt][0]), "r"(b[nt][1]));
                }
        }
        __syncthreads();
        if (t + 3 < NIT) fill(t + 3);
    }

    // epilogue
#pragma unroll
    for (int mt = 0; mt < 2; mt++) {
        int r0 = bm + wm + mt * 16 + g;
#pragma unroll
        for (int nt = 0; nt < 8; nt++) {
            int col = bn + wn + nt * 8 + tig * 2;
            float x0 = c[mt][nt][0], x1 = c[mt][nt][1];
            float x2 = c[mt][nt][2], x3 = c[mt][nt][3];
            if (SILU) {
                x0 = x0 / (1.f + __expf(-x0));
                x1 = x1 / (1.f + __expf(-x1));
                x2 = x2 / (1.f + __expf(-x2));
                x3 = x3 / (1.f + __expf(-x3));
            }
            *(float2*)(C + (long)r0 * N + col)       = make_float2(x0, x1);
            *(float2*)(C + (long)(r0 + 8) * N + col) = make_float2(x2, x3);
        }
    }
}

// ---------------- fused low-rank stage 1: both gates, hs read once ----------
__global__ __launch_bounds__(256) void lowrank1_fused_kernel(
    const float* __restrict__ A, const float* __restrict__ W1,
    const float* __restrict__ W2, float* __restrict__ R1,
    float* __restrict__ R2, int K)
{
    const int warp = threadIdx.x >> 5;
    const int lane = threadIdx.x & 31;
    const int m = blockIdx.x * 8 + warp;
    const float* ap = A + (long)m * K;

    float acc1[16], acc2[16];
#pragma unroll
    for (int n = 0; n < 16; n++) { acc1[n] = 0.f; acc2[n] = 0.f; }

    for (int k = lane; k < K; k += 32) {
        float a = ap[k];
        const float4* w1 = (const float4*)(W1 + (long)k * 16);
        const float4* w2 = (const float4*)(W2 + (long)k * 16);
#pragma unroll
        for (int q = 0; q < 4; q++) {
            float4 u = w1[q];
            acc1[q*4+0] += a * u.x; acc1[q*4+1] += a * u.y;
            acc1[q*4+2] += a * u.z; acc1[q*4+3] += a * u.w;
            float4 v = w2[q];
            acc2[q*4+0] += a * v.x; acc2[q*4+1] += a * v.y;
            acc2[q*4+2] += a * v.z; acc2[q*4+3] += a * v.w;
        }
    }
#pragma unroll
    for (int n = 0; n < 16; n++) {
        float v = acc1[n];
        v += __shfl_xor_sync(0xffffffffu, v, 16);
        v += __shfl_xor_sync(0xffffffffu, v, 8);
        v += __shfl_xor_sync(0xffffffffu, v, 4);
        v += __shfl_xor_sync(0xffffffffu, v, 2);
        v += __shfl_xor_sync(0xffffffffu, v, 1);
        if (lane == 0) R1[(long)m * 16 + n] = v;
        float w = acc2[n];
        w += __shfl_xor_sync(0xffffffffu, w, 16);
        w += __shfl_xor_sync(0xffffffffu, w, 8);
        w += __shfl_xor_sync(0xffffffffu, w, 4);
        w += __shfl_xor_sync(0xffffffffu, w, 2);
        w += __shfl_xor_sync(0xffffffffu, w, 1);
        if (lane == 0) R2[(long)m * 16 + n] = w;
    }
}

// ---------------- low-rank stage 2: Out = act(R[M,16] @ W2[16,N] + b) --------
__global__ __launch_bounds__(256) void lowrank2_kernel(
    const float* __restrict__ Rt, const float* __restrict__ W2,
    const float* __restrict__ bias, float* __restrict__ Out,
    int NOUT, int mode)
{
    int idx = blockIdx.x * 256 + threadIdx.x;
    int m = idx / NOUT;
    int n = idx - m * NOUT;
    const float* r = Rt + (long)m * 16;
    float acc = bias[n];
#pragma unroll
    for (int j = 0; j < 16; j++) acc += r[j] * W2[(long)j * NOUT + n];
    if (mode) {
        float x = acc;
        float ls = (x >= 0.f) ? -log1pf(__expf(-x)) : (x - log1pf(__expf(x)));
        acc = ls * GLN_INV;
    }
    Out[idx] = acc;
}

// ---------------- GLA chunked recurrence ----------------
#define OFF_Q  0
#define OFF_K  4160
#define OFF_A  8320
#define OFF_V  12480
#define OFF_S  14592
#define OFF_GL 16704
#define SM_FLOATS 16768
#define SM_BYTES  (SM_FLOATS * 4)

__global__ __launch_bounds__(256) void gla_kernel(
    const float* __restrict__ Q, const float* __restrict__ Kx,
    const float* __restrict__ V, const float* __restrict__ GK,
    float* __restrict__ O)
{
    extern __shared__ float sm[];
    float* sq  = sm + OFF_Q;
    float* sk  = sm + OFF_K;
    float* sA  = sm + OFF_A;
    float* sv  = sm + OFF_V;
    float* sS  = sm + OFF_S;
    float* sGl = sm + OFF_GL;

    const int tid = threadIdx.x;
    const int s  = blockIdx.x & 3;
    const int bh = blockIdx.x >> 2;
    const int h  = bh & 15;
    const int b  = bh >> 4;
    const int e0 = s * 32;

    const int cb = tid & 63;
    const int eg = tid >> 6;

    for (int i = tid; i < 64 * 33; i += 256) sS[i] = 0.f;

    for (int ch = 0; ch < NCC; ch++) {
        __syncthreads();
        const long base = ((long)(b * TT + ch * 64) * HH + h);
        const float* qp  = Q  + base * DKq;
        const float* kp  = Kx + base * DKq;
        const float* gp  = GK + base * DKq;
        const float* vp  = V  + base * DVv + e0;

#pragma unroll
        for (int w = 0; w < 4; w++) {
            int f = w * 256 + tid;
            int c = f >> 4;
            int dq = (f & 15) << 2;
            float4 a4 = *(const float4*)(qp + (long)c * 1024 + dq);
            sq[c*65+dq]=a4.x; sq[c*65+dq+1]=a4.y; sq[c*65+dq+2]=a4.z; sq[c*65+dq+3]=a4.w;
            float4 b4 = *(const float4*)(kp + (long)c * 1024 + dq);
            sk[c*65+dq]=b4.x; sk[c*65+dq+1]=b4.y; sk[c*65+dq+2]=b4.z; sk[c*65+dq+3]=b4.w;
            float4 g4 = *(const float4*)(gp + (long)c * 1024 + dq);
            sA[c*65+dq]=g4.x; sA[c*65+dq+1]=g4.y; sA[c*65+dq+2]=g4.z; sA[c*65+dq+3]=g4.w;
        }
#pragma unroll
        for (int w = 0; w < 2; w++) {
            int f = w * 256 + tid;
            int c = f >> 3;
            int eq = (f & 7) << 2;
            float4 v4 = *(const float4*)(vp + (long)c * 2048 + eq);
            sv[c*33+eq]=v4.x; sv[c*33+eq+1]=v4.y; sv[c*33+eq+2]=v4.z; sv[c*33+eq+3]=v4.w;
        }
        __syncthreads();

        if (tid < 64) {
            int d = tid;
            float acc = 0.f;
            for (int c = 0; c < 64; c++) {
                acc += sA[c*65 + d];
                sA[c*65 + d] = acc;
            }
            sGl[d] = acc;
        }
        __syncthreads();

#pragma unroll
        for (int w = 0; w < 16; w++) {
            int f = w * 256 + tid;
            int c = f >> 6;
            int d = f & 63;
            float G = sA[c*65 + d];
            sq[c*65 + d] *= __expf(G) * 0.125f;
            sk[c*65 + d] *= __expf(-G);
        }
        if (tid < 64) sGl[tid] = __expf(sGl[tid]);
        __syncthreads();

        float o_r[8];
#pragma unroll
        for (int j = 0; j < 8; j++) o_r[j] = 0.f;
        {
            const int c = cb;
#pragma unroll 4
            for (int d = 0; d < 64; d++) {
                float qv = sq[c*65 + d];
                const float* Srow = &sS[d*33 + eg*8];
#pragma unroll
                for (int j = 0; j < 8; j++) o_r[j] += qv * Srow[j];
            }
        }
        {
            const int c = cb;
            const int jbase = eg * 16;
            float a[16];
#pragma unroll
            for (int jj = 0; jj < 16; jj++) a[jj] = 0.f;
#pragma unroll 2
            for (int d = 0; d < 64; d++) {
                float qv = sq[c*65 + d];
#pragma unroll
                for (int jj = 0; jj < 16; jj++)
                    a[jj] += qv * sk[(jbase + jj)*65 + d];
            }
#pragma unroll
            for (int jj = 0; jj < 16; jj++)
                sA[c*65 + jbase + jj] = (jbase + jj <= c) ? a[jj] : 0.f;
        }
        __syncthreads();

        {
            const int c = cb;
            for (int j64 = 0; j64 <= c; j64++) {
                float a = sA[c*65 + j64];
                const float* vr = &sv[j64*33 + eg*8];
#pragma unroll
                for (int j = 0; j < 8; j++) o_r[j] += a * vr[j];
            }
            float* op = O + (base + (long)c * HH) * DVv + e0 + eg * 8;
            float4 w0 = make_float4(o_r[0], o_r[1], o_r[2], o_r[3]);
            float4 w1 = make_float4(o_r[4], o_r[5], o_r[6], o_r[7]);
            *(float4*)(op)     = w0;
            *(float4*)(op + 4) = w1;
        }
        {
            const int d = cb;
            float* Srow = &sS[d*33 + eg*8];
            float acc[8];
#pragma unroll
            for (int j = 0; j < 8; j++) acc[j] = Srow[j];
#pragma unroll 4
            for (int c64 = 0; c64 < 64; c64++) {
                float kv = sk[c64*65 + d];
                const float* vr = &sv[c64*33 + eg*8];
#pragma unroll
                for (int j = 0; j < 8; j++) acc[j] += kv * vr[j];
            }
            float eGl = sGl[d];
#pragma unroll
            for (int j = 0; j < 8; j++) Srow[j] = acc[j] * eGl;
        }
    }
}

// ---------------- RMS norm + sigmoid gate -> fp16 output ---------------------
__global__ __launch_bounds__(256) void rmsgate_kernel(
    const float* __restrict__ O, const float* __restrict__ G,
    const float* __restrict__ gw, __half* __restrict__ OH)
{
    int row = blockIdx.x * 8 + (threadIdx.x >> 5);   // (b*T+t)*16 + h
    int lane = threadIdx.x & 31;
    long basei = (long)row * 128 + lane * 4;
    float4 o4 = *(const float4*)&O[basei];
    float ss = o4.x*o4.x + o4.y*o4.y + o4.z*o4.z + o4.w*o4.w;
    ss += __shfl_xor_sync(0xffffffffu, ss, 16);
    ss += __shfl_xor_sync(0xffffffffu, ss, 8);
    ss += __shfl_xor_sync(0xffffffffu, ss, 4);
    ss += __shfl_xor_sync(0xffffffffu, ss, 2);
    ss += __shfl_xor_sync(0xffffffffu, ss, 1);
    float rr = rsqrtf(ss * (1.f / 128.f) + EPSL);
    float4 g4 = *(const float4*)&G[basei];
    float4 w4 = *(const float4*)&gw[lane * 4];
    float r0 = o4.x * rr * w4.x / (1.f + __expf(-g4.x));
    float r1 = o4.y * rr * w4.y / (1.f + __expf(-g4.y));
    float r2 = o4.z * rr * w4.z / (1.f + __expf(-g4.z));
    float r3 = o4.w * rr * w4.w / (1.f + __expf(-g4.w));
    // output row-major [M][2048]: m = row>>4, col = (row&15)*128 + lane*4
    long oidx = (long)(row >> 4) * 2048 + (row & 15) * 128 + lane * 4;
    __half2 h0 = __floats2half2_rn(r0, r1);
    __half2 h1 = __floats2half2_rn(r2, r3);
    uint2 pack;
    pack.x = *(uint32_t*)&h0;
    pack.y = *(uint32_t*)&h1;
    *(uint2*)&OH[oidx] = pack;
}

// ---------------- launch ----------------
extern "C" void kernel_launch(void* const* d_in, const int* in_sizes, int n_in,
                              void* d_out, int out_size)
{
    const float* hs    = (const float*)d_in[0];
    const float* Wq    = (const float*)d_in[1];
    const float* Wk    = (const float*)d_in[2];
    const float* Wv    = (const float*)d_in[3];
    const float* Wgk1  = (const float*)d_in[4];
    const float* Wgk2  = (const float*)d_in[5];
    const float* bgk2  = (const float*)d_in[6];
    const float* Wg1   = (const float*)d_in[7];
    const float* Wg2   = (const float*)d_in[8];
    const float* bg2   = (const float*)d_in[9];
    const float* Wo    = (const float*)d_in[10];
    const float* gnw   = (const float*)d_in[11];
    float* out = (float*)d_out;

    float *pq, *pk, *pv, *pgk, *pr1, *pr2, *pg, *po;
    __half *phsh, *pwqh, *pwkh, *pwvh, *pwoh, *poh;
    cudaGetSymbolAddress((void**)&pq,  g_q);
    cudaGetSymbolAddress((void**)&pk,  g_k);
    cudaGetSymbolAddress((void**)&pv,  g_v);
    cudaGetSymbolAddress((void**)&pgk, g_gk);
    cudaGetSymbolAddress((void**)&pr1, g_r1);
    cudaGetSymbolAddress((void**)&pr2, g_r2);
    cudaGetSymbolAddress((void**)&pg,  g_g);
    cudaGetSymbolAddress((void**)&po,  g_o);
    cudaGetSymbolAddress((void**)&phsh, g_hsh);
    cudaGetSymbolAddress((void**)&pwqh, g_wqh);
    cudaGetSymbolAddress((void**)&pwkh, g_wkh);
    cudaGetSymbolAddress((void**)&pwvh, g_wvh);
    cudaGetSymbolAddress((void**)&pwoh, g_woh);
    cudaGetSymbolAddress((void**)&poh,  g_oh);

    cudaFuncSetAttribute(h16gemm_kernel<true>,  cudaFuncAttributeMaxDynamicSharedMemorySize, HSM_BYTES);
    cudaFuncSetAttribute(h16gemm_kernel<false>, cudaFuncAttributeMaxDynamicSharedMemorySize, HSM_BYTES);
    cudaFuncSetAttribute(gla_kernel, cudaFuncAttributeMaxDynamicSharedMemorySize, SM_BYTES);

    // 1: hs -> fp16
    to_half_kernel<<<(MM*DD/4 + 255)/256, 256>>>(hs, phsh, MM*DD/4);
    // 2-5: transpose+convert weights -> [N][K] fp16
    {
        dim3 blk(32, 8);
        transpose_half_kernel<<<dim3(NQK/32, DD/32), blk>>>(Wq, pwqh, DD, NQK);
        transpose_half_kernel<<<dim3(NQK/32, DD/32), blk>>>(Wk, pwkh, DD, NQK);
        transpose_half_kernel<<<dim3(NV/32,  DD/32), blk>>>(Wv, pwvh, DD, NV);
        transpose_half_kernel<<<dim3(DD/32,  NV/32), blk>>>(Wo, pwoh, NV, DD);
    }
    // 6: fused q+k projections (gridDim.z=2), 7: v projection
    {
        dim3 grid(NQK / 256, MM / 128, 2);
        h16gemm_kernel<true><<<grid, 512, HSM_BYTES>>>(phsh, pwqh, pwkh, pq, pk, MM, NQK, DD);
    }
    {
        dim3 grid(NV / 256, MM / 128, 1);
        h16gemm_kernel<true><<<grid, 512, HSM_BYTES>>>(phsh, pwvh, pwvh, pv, pv, MM, NV, DD);
    }
    // fused low-rank stage 1 (hs read once), then stage 2 per gate
    lowrank1_fused_kernel<<<MM / 8, 256>>>(hs, Wgk1, Wg1, pr1, pr2, DD);
    lowrank2_kernel<<<(MM * NQK) / 256, 256>>>(pr1, Wgk2, bgk2, pgk, NQK, 1);
    lowrank2_kernel<<<(MM * NV) / 256, 256>>>(pr2, Wg2, bg2, pg, NV, 0);

    // chunked GLA
    gla_kernel<<<BB * HH * 4, 256, SM_BYTES>>>(pq, pk, pv, pgk, po);

    // rms norm + gate -> fp16 o
    rmsgate_kernel<<<(MM * HH) / 8, 256>>>(po, pg, gnw, poh);

    // output projection
    {
        dim3 grid(DD / 256, MM / 128, 1);
        h16gemm_kernel<false><<<grid, 512, HSM_BYTES>>>(poh, pwoh, pwoh, out, out, MM, DD, NV);
    }
    (void)in_sizes; (void)n_in; (void)out_size;
}

// round 9
// speedup vs baseline: 1.5432x; 1.5432x over previous
#include <cuda_runtime.h>
#include <cuda_bf16.h>
#include <math.h>
#include <stdint.h>

// Problem constants
#define BB 2
#define TT 2048
#define DD 2048
#define HH 16
#define DKq 64
#define DVv 128
#define RR 16
#define CC 64
#define NCC 32
#define MM (BB*TT)          // 4096
#define NQK (HH*DKq)        // 1024
#define NV  (HH*DVv)        // 2048
#define GLN_INV (1.0f/16.0f)
#define EPSL 1e-5f

// ---------------- scratch (device globals, no allocs allowed) ----------------
__device__ float g_q [MM*NQK];
__device__ float g_k [MM*NQK];
__device__ float g_v [MM*NV];
__device__ float g_gk[MM*NQK];
__device__ float g_r1[MM*RR];
__device__ float g_r2[MM*RR];
__device__ float g_g [MM*NV];
__device__ float g_o [MM*NV];
__device__ float g_hsr[MM*DD];     // tf32-rounded + permuted hs
__device__ float g_wqr[DD*NQK];    // transposed [N][K] + permuted + rounded
__device__ float g_wkr[DD*NQK];
__device__ float g_wvr[DD*NV];
__device__ float g_wor[NV*DD];

// ---------------- helpers ----------------
__device__ __forceinline__ float f2tf32(float x) {
    uint32_t r;
    asm("cvt.rna.tf32.f32 %0, %1;" : "=r"(r) : "f"(x));
    return __uint_as_float(r);
}

__device__ __forceinline__ void cp16(void* smem_dst, const void* gmem_src) {
    uint32_t s = (uint32_t)__cvta_generic_to_shared(smem_dst);
    asm volatile("cp.async.cg.shared.global [%0], [%1], 16;" :: "r"(s), "l"(gmem_src));
}

// permutation within each 32-float K block: p(c) = (c&3)*8 + (c>>2)
// inverse: c(p) = (p&7)*4 + (p>>3)

// round hs to tf32 + permute
__global__ __launch_bounds__(256) void round_perm_kernel(
    const float* __restrict__ src, float* __restrict__ dst, int n4, int Kdim)
{
    int idx = blockIdx.x * 256 + threadIdx.x;
    if (idx >= n4) return;
    int q4 = Kdim >> 2;
    int m = idx / q4;
    int q = idx - m * q4;
    int kb = q >> 3;
    int j  = q & 7;
    const float* s = src + (long)m * Kdim + kb * 32;
    float4 o;
    int p0 = 4 * j;
    o.x = f2tf32(s[((p0    ) & 7) * 4 + ((p0    ) >> 3)]);
    o.y = f2tf32(s[((p0 + 1) & 7) * 4 + ((p0 + 1) >> 3)]);
    o.z = f2tf32(s[((p0 + 2) & 7) * 4 + ((p0 + 2) >> 3)]);
    o.w = f2tf32(s[((p0 + 3) & 7) * 4 + ((p0 + 3) >> 3)]);
    *(float4*)(dst + (long)m * Kdim + kb * 32 + p0) = o;
}

// transpose + round + permute: W[K][N] -> WT[n][kb*32 + p]
__global__ __launch_bounds__(256) void transpose_perm_kernel(
    const float* __restrict__ W, float* __restrict__ WT, int K, int N)
{
    __shared__ float t[32][33];
    const int tx = threadIdx.x;       // 0..31
    const int ty = threadIdx.y;       // 0..7
    const int n0 = blockIdx.x * 32;
    const int k0 = blockIdx.y * 32;
#pragma unroll
    for (int i = 0; i < 4; i++)
        t[ty + 8*i][tx] = W[(long)(k0 + ty + 8*i) * N + n0 + tx];
    __syncthreads();
    int p0 = 4 * ty;
    float4 o;
    o.x = f2tf32(t[((p0    ) & 7) * 4 + ((p0    ) >> 3)][tx]);
    o.y = f2tf32(t[((p0 + 1) & 7) * 4 + ((p0 + 1) >> 3)][tx]);
    o.z = f2tf32(t[((p0 + 2) & 7) * 4 + ((p0 + 2) >> 3)][tx]);
    o.w = f2tf32(t[((p0 + 3) & 7) * 4 + ((p0 + 3) >> 3)][tx]);
    *(float4*)(WT + (long)(n0 + tx) * K + k0 + p0) = o;
}

// ---------------- tf32 mma.sync GEMM v4 ----------------
// C = act(A'[M,K] @ BT'[N,K]^T), operands in permuted tf32 layout.
// BM=128, BN=256, BK=32. 512 threads (16 warps), warp tile 32x64.
// 3-stage cp.async ring; rows are 128B, chunk (16B) swizzled by j^(row&7).
// Fragment loads: LDS.128, conflict-free per 8-lane phase.
#define PSTAGE_A (128*32)                 // floats
#define PSTAGE_B (256*32)
#define PSTAGE_FLOATS (PSTAGE_A + PSTAGE_B)   // 12288
#define PSM_BYTES (3*PSTAGE_FLOATS*4)         // 147456

template<bool SILU>
__global__ __launch_bounds__(512, 1) void tf32gemm4_kernel(
    const float* __restrict__ A, const float* __restrict__ BT,
    float* __restrict__ C, int M, int N, int K)
{
    extern __shared__ float sm[];
    const int tid  = threadIdx.x;
    const int warp = tid >> 5;
    const int lane = tid & 31;
    const int g    = lane >> 2;          // 0..7
    const int tig  = lane & 3;           // 0..3
    const int wm   = (warp >> 2) * 32;   // 0,32,64,96
    const int wn   = (warp & 3) * 64;    // 0,64,128,192
    const int bm   = blockIdx.y * 128;
    const int bn   = blockIdx.x * 256;
    const int NIT  = K >> 5;

    float c[2][8][4];
#pragma unroll
    for (int mt = 0; mt < 2; mt++)
#pragma unroll
        for (int nt = 0; nt < 8; nt++)
#pragma unroll
            for (int r = 0; r < 4; r++) c[mt][nt][r] = 0.f;

    auto fill = [&](int t) {
        char* As = (char*)(sm + (t % 3) * PSTAGE_FLOATS);
        char* Bs = As + PSTAGE_A * 4;
        const int kbase = t << 5;
        // A: 128 rows x 8 chunks = 1024, 2/thread
#pragma unroll
        for (int i = 0; i < 2; i++) {
            int idx = tid + i * 512;
            int row = idx >> 3;
            int j   = idx & 7;
            cp16(As + row * 128 + ((j ^ (row & 7)) << 4),
                 A + (long)(bm + row) * K + kbase + j * 4);
        }
        // B: 256 rows x 8 chunks = 2048, 4/thread
#pragma unroll
        for (int i = 0; i < 4; i++) {
            int idx = tid + i * 512;
            int row = idx >> 3;
            int j   = idx & 7;
            cp16(Bs + row * 128 + ((j ^ (row & 7)) << 4),
                 BT + (long)(bn + row) * K + kbase + j * 4);
        }
        asm volatile("cp.async.commit_group;");
    };

    fill(0); fill(1); fill(2);

    for (int t = 0; t < NIT; t++) {
        int rem = NIT - 1 - t;
        if (rem >= 2)      asm volatile("cp.async.wait_group 2;");
        else if (rem == 1) asm volatile("cp.async.wait_group 1;");
        else               asm volatile("cp.async.wait_group 0;");
        __syncthreads();

        const char* Ab = (const char*)(sm + (t % 3) * PSTAGE_FLOATS);
        const char* Bb = Ab + PSTAGE_A * 4;

#pragma unroll
        for (int h = 0; h < 2; h++) {
            const int ch = ((2 * tig + h) ^ g) << 4;   // all frag rows ≡ g (mod 8)
            float4 av[2][2];
#pragma unroll
            for (int mt = 0; mt < 2; mt++) {
                int r1 = wm + mt * 16 + g;
                av[mt][0] = *(const float4*)(Ab + r1 * 128 + ch);
                av[mt][1] = *(const float4*)(Ab + (r1 + 8) * 128 + ch);
            }
#pragma unroll
            for (int ntp = 0; ntp < 4; ntp++) {
                float4 bv[2];
#pragma unroll
                for (int u = 0; u < 2; u++) {
                    int rn = wn + (ntp * 2 + u) * 8 + g;
                    bv[u] = *(const float4*)(Bb + rn * 128 + ch);
                }
#pragma unroll
                for (int u = 0; u < 2; u++) {
                    int nt = ntp * 2 + u;
#pragma unroll
                    for (int mt = 0; mt < 2; mt++) {
                        // ks = 2h
                        asm volatile(
                            "mma.sync.aligned.m16n8k8.row.col.f32.tf32.tf32.f32 "
                            "{%0,%1,%2,%3}, {%4,%5,%6,%7}, {%8,%9}, {%0,%1,%2,%3};"
                            : "+f"(c[mt][nt][0]), "+f"(c[mt][nt][1]),
                              "+f"(c[mt][nt][2]), "+f"(c[mt][nt][3])
                            : "r"(__float_as_uint(av[mt][0].x)), "r"(__float_as_uint(av[mt][1].x)),
                              "r"(__float_as_uint(av[mt][0].y)), "r"(__float_as_uint(av[mt][1].y)),
                              "r"(__float_as_uint(bv[u].x)), "r"(__float_as_uint(bv[u].y)));
                        // ks = 2h+1
                        asm volatile(
                            "mma.sync.aligned.m16n8k8.row.col.f32.tf32.tf32.f32 "
                            "{%0,%1,%2,%3}, {%4,%5,%6,%7}, {%8,%9}, {%0,%1,%2,%3};"
                            : "+f"(c[mt][nt][0]), "+f"(c[mt][nt][1]),
                              "+f"(c[mt][nt][2]), "+f"(c[mt][nt][3])
                            : "r"(__float_as_uint(av[mt][0].z)), "r"(__float_as_uint(av[mt][1].z)),
                              "r"(__float_as_uint(av[mt][0].w)), "r"(__float_as_uint(av[mt][1].w)),
                              "r"(__float_as_uint(bv[u].z)), "r"(__float_as_uint(bv[u].w)));
                    }
                }
            }
        }
        __syncthreads();
        if (t + 3 < NIT) fill(t + 3);
    }

    // epilogue
#pragma unroll
    for (int mt = 0; mt < 2; mt++) {
        int r0 = bm + wm + mt * 16 + g;
#pragma unroll
        for (int nt = 0; nt < 8; nt++) {
            int col = bn + wn + nt * 8 + tig * 2;
            float x0 = c[mt][nt][0], x1 = c[mt][nt][1];
            float x2 = c[mt][nt][2], x3 = c[mt][nt][3];
            if (SILU) {
                x0 = x0 / (1.f + __expf(-x0));
                x1 = x1 / (1.f + __expf(-x1));
                x2 = x2 / (1.f + __expf(-x2));
                x3 = x3 / (1.f + __expf(-x3));
            }
            *(float2*)(C + (long)r0 * N + col)       = make_float2(x0, x1);
            *(float2*)(C + (long)(r0 + 8) * N + col) = make_float2(x2, x3);
        }
    }
}

// ---------------- fused low-rank stage 1: both gates, hs read once ----------
__global__ __launch_bounds__(256) void lowrank1_fused_kernel(
    const float* __restrict__ A, const float* __restrict__ W1,
    const float* __restrict__ W2, float* __restrict__ R1,
    float* __restrict__ R2, int K)
{
    const int warp = threadIdx.x >> 5;
    const int lane = threadIdx.x & 31;
    const int m = blockIdx.x * 8 + warp;
    const float* ap = A + (long)m * K;

    float acc1[16], acc2[16];
#pragma unroll
    for (int n = 0; n < 16; n++) { acc1[n] = 0.f; acc2[n] = 0.f; }

    for (int k = lane; k < K; k += 32) {
        float a = ap[k];
        const float4* w1 = (const float4*)(W1 + (long)k * 16);
        const float4* w2 = (const float4*)(W2 + (long)k * 16);
#pragma unroll
        for (int q = 0; q < 4; q++) {
            float4 u = w1[q];
            acc1[q*4+0] += a * u.x; acc1[q*4+1] += a * u.y;
            acc1[q*4+2] += a * u.z; acc1[q*4+3] += a * u.w;
            float4 v = w2[q];
            acc2[q*4+0] += a * v.x; acc2[q*4+1] += a * v.y;
            acc2[q*4+2] += a * v.z; acc2[q*4+3] += a * v.w;
        }
    }
#pragma unroll
    for (int n = 0; n < 16; n++) {
        float v = acc1[n];
        v += __shfl_xor_sync(0xffffffffu, v, 16);
        v += __shfl_xor_sync(0xffffffffu, v, 8);
        v += __shfl_xor_sync(0xffffffffu, v, 4);
        v += __shfl_xor_sync(0xffffffffu, v, 2);
        v += __shfl_xor_sync(0xffffffffu, v, 1);
        if (lane == 0) R1[(long)m * 16 + n] = v;
        float w = acc2[n];
        w += __shfl_xor_sync(0xffffffffu, w, 16);
        w += __shfl_xor_sync(0xffffffffu, w, 8);
        w += __shfl_xor_sync(0xffffffffu, w, 4);
        w += __shfl_xor_sync(0xffffffffu, w, 2);
        w += __shfl_xor_sync(0xffffffffu, w, 1);
        if (lane == 0) R2[(long)m * 16 + n] = w;
    }
}

// ---------------- low-rank stage 2 ----------------
__global__ __launch_bounds__(256) void lowrank2_kernel(
    const float* __restrict__ Rt, const float* __restrict__ W2,
    const float* __restrict__ bias, float* __restrict__ Out,
    int NOUT, int mode)
{
    int idx = blockIdx.x * 256 + threadIdx.x;
    int m = idx / NOUT;
    int n = idx - m * NOUT;
    const float* r = Rt + (long)m * 16;
    float acc = bias[n];
#pragma unroll
    for (int j = 0; j < 16; j++) acc += r[j] * W2[(long)j * NOUT + n];
    if (mode) {
        float x = acc;
        float ls = (x >= 0.f) ? -log1pf(__expf(-x)) : (x - log1pf(__expf(x)));
        acc = ls * GLN_INV;
    }
    Out[idx] = acc;
}

// ---------------- GLA chunked recurrence (512 threads) ----------------
#define OFF_Q  0
#define OFF_K  4160
#define OFF_A  8320
#define OFF_V  12480
#define OFF_S  14592
#define OFF_GL 16704
#define SM_FLOATS 16768
#define SM_BYTES  (SM_FLOATS * 4)

__global__ __launch_bounds__(512) void gla_kernel(
    const float* __restrict__ Q, const float* __restrict__ Kx,
    const float* __restrict__ V, const float* __restrict__ GK,
    float* __restrict__ O)
{
    extern __shared__ float sm[];
    float* sq  = sm + OFF_Q;
    float* sk  = sm + OFF_K;
    float* sA  = sm + OFF_A;
    float* sv  = sm + OFF_V;
    float* sS  = sm + OFF_S;
    float* sGl = sm + OFF_GL;

    const int tid = threadIdx.x;
    const int s  = blockIdx.x & 3;
    const int bh = blockIdx.x >> 2;
    const int h  = bh & 15;
    const int b  = bh >> 4;
    const int e0 = s * 32;

    const int cb = tid & 63;    // c-row (or d-row) role
    const int eg = tid >> 6;    // 0..7, owns e = eg*4..eg*4+3

    for (int i = tid; i < 64 * 33; i += 512) sS[i] = 0.f;

    for (int ch = 0; ch < NCC; ch++) {
        __syncthreads();
        const long base = ((long)(b * TT + ch * 64) * HH + h);
        const float* qp  = Q  + base * DKq;
        const float* kp  = Kx + base * DKq;
        const float* gp  = GK + base * DKq;
        const float* vp  = V  + base * DVv + e0;

#pragma unroll
        for (int w = 0; w < 2; w++) {
            int f = w * 512 + tid;          // 0..1023
            int c = f >> 4;
            int dq = (f & 15) << 2;
            float4 a4 = *(const float4*)(qp + (long)c * 1024 + dq);
            sq[c*65+dq]=a4.x; sq[c*65+dq+1]=a4.y; sq[c*65+dq+2]=a4.z; sq[c*65+dq+3]=a4.w;
            float4 b4 = *(const float4*)(kp + (long)c * 1024 + dq);
            sk[c*65+dq]=b4.x; sk[c*65+dq+1]=b4.y; sk[c*65+dq+2]=b4.z; sk[c*65+dq+3]=b4.w;
            float4 g4 = *(const float4*)(gp + (long)c * 1024 + dq);
            sA[c*65+dq]=g4.x; sA[c*65+dq+1]=g4.y; sA[c*65+dq+2]=g4.z; sA[c*65+dq+3]=g4.w;
        }
        {
            int f = tid;                    // 0..511
            int c = f >> 3;
            int eq = (f & 7) << 2;
            float4 v4 = *(const float4*)(vp + (long)c * 2048 + eq);
            sv[c*33+eq]=v4.x; sv[c*33+eq+1]=v4.y; sv[c*33+eq+2]=v4.z; sv[c*33+eq+3]=v4.w;
        }
        __syncthreads();

        if (tid < 64) {
            int d = tid;
            float acc = 0.f;
            for (int c = 0; c < 64; c++) {
                acc += sA[c*65 + d];
                sA[c*65 + d] = acc;
            }
            sGl[d] = acc;
        }
        __syncthreads();

#pragma unroll
        for (int w = 0; w < 8; w++) {
            int f = w * 512 + tid;
            int c = f >> 6;
            int d = f & 63;
            float G = sA[c*65 + d];
            sq[c*65 + d] *= __expf(G) * 0.125f;
            sk[c*65 + d] *= __expf(-G);
        }
        if (tid < 64) sGl[tid] = __expf(sGl[tid]);
        __syncthreads();

        float o_r[4];
#pragma unroll
        for (int j = 0; j < 4; j++) o_r[j] = 0.f;
        {
            const int c = cb;
#pragma unroll 4
            for (int d = 0; d < 64; d++) {
                float qv = sq[c*65 + d];
                const float* Srow = &sS[d*33 + eg*4];
#pragma unroll
                for (int j = 0; j < 4; j++) o_r[j] += qv * Srow[j];
            }
        }
        {
            const int c = cb;
            const int jbase = eg * 8;
            float a[8];
#pragma unroll
            for (int jj = 0; jj < 8; jj++) a[jj] = 0.f;
#pragma unroll 2
            for (int d = 0; d < 64; d++) {
                float qv = sq[c*65 + d];
#pragma unroll
                for (int jj = 0; jj < 8; jj++)
                    a[jj] += qv * sk[(jbase + jj)*65 + d];
            }
#pragma unroll
            for (int jj = 0; jj < 8; jj++)
                sA[c*65 + jbase + jj] = (jbase + jj <= c) ? a[jj] : 0.f;
        }
        __syncthreads();

        {
            const int c = cb;
            for (int j64 = 0; j64 <= c; j64++) {
                float a = sA[c*65 + j64];
                const float* vr = &sv[j64*33 + eg*4];
#pragma unroll
                for (int j = 0; j < 4; j++) o_r[j] += a * vr[j];
            }
            float* op = O + (base + (long)c * HH) * DVv + e0 + eg * 4;
            *(float4*)(op) = make_float4(o_r[0], o_r[1], o_r[2], o_r[3]);
        }
        {
            const int d = cb;
            float* Srow = &sS[d*33 + eg*4];
            float acc[4];
#pragma unroll
            for (int j = 0; j < 4; j++) acc[j] = Srow[j];
#pragma unroll 4
            for (int c64 = 0; c64 < 64; c64++) {
                float kv = sk[c64*65 + d];
                const float* vr = &sv[c64*33 + eg*4];
#pragma unroll
                for (int j = 0; j < 4; j++) acc[j] += kv * vr[j];
            }
            float eGl = sGl[d];
#pragma unroll
            for (int j = 0; j < 4; j++) Srow[j] = acc[j] * eGl;
        }
    }
}

// ---------------- RMS norm + sigmoid gate, in-place tf32 + permuted ----------
__global__ __launch_bounds__(256) void rmsgate_kernel(
    float* __restrict__ O, const float* __restrict__ G,
    const float* __restrict__ gw)
{
    int row = blockIdx.x * 8 + (threadIdx.x >> 5);   // (b*T+t)*16 + h
    int lane = threadIdx.x & 31;
    long basei = (long)row * 128 + lane * 4;
    float4 o4 = *(float4*)&O[basei];
    float ss = o4.x*o4.x + o4.y*o4.y + o4.z*o4.z + o4.w*o4.w;
    ss += __shfl_xor_sync(0xffffffffu, ss, 16);
    ss += __shfl_xor_sync(0xffffffffu, ss, 8);
    ss += __shfl_xor_sync(0xffffffffu, ss, 4);
    ss += __shfl_xor_sync(0xffffffffu, ss, 2);
    ss += __shfl_xor_sync(0xffffffffu, ss, 1);
    float rr = rsqrtf(ss * (1.f / 128.f) + EPSL);
    float4 g4 = *(const float4*)&G[basei];
    float4 w4 = *(const float4*)&gw[lane * 4];
    float r0 = f2tf32(o4.x * rr * w4.x / (1.f + __expf(-g4.x)));
    float r1 = f2tf32(o4.y * rr * w4.y / (1.f + __expf(-g4.y)));
    float r2 = f2tf32(o4.z * rr * w4.z / (1.f + __expf(-g4.z)));
    float r3 = f2tf32(o4.w * rr * w4.w / (1.f + __expf(-g4.w)));
    // permuted scatter (within this row's own 128-float segment; warp-safe):
    // K block kb = h*4 + (lane>>3), positions p = i*8 + (lane&7)
    long obase = (long)(row >> 4) * 2048 + ((row & 15) * 4 + (lane >> 3)) * 32 + (lane & 7);
    O[obase + 0 ] = r0;
    O[obase + 8 ] = r1;
    O[obase + 16] = r2;
    O[obase + 24] = r3;
}

// ---------------- launch ----------------
extern "C" void kernel_launch(void* const* d_in, const int* in_sizes, int n_in,
                              void* d_out, int out_size)
{
    const float* hs    = (const float*)d_in[0];
    const float* Wq    = (const float*)d_in[1];
    const float* Wk    = (const float*)d_in[2];
    const float* Wv    = (const float*)d_in[3];
    const float* Wgk1  = (const float*)d_in[4];
    const float* Wgk2  = (const float*)d_in[5];
    const float* bgk2  = (const float*)d_in[6];
    const float* Wg1   = (const float*)d_in[7];
    const float* Wg2   = (const float*)d_in[8];
    const float* bg2   = (const float*)d_in[9];
    const float* Wo    = (const float*)d_in[10];
    const float* gnw   = (const float*)d_in[11];
    float* out = (float*)d_out;

    float *pq, *pk, *pv, *pgk, *pr1, *pr2, *pg, *po;
    float *phsr, *pwqr, *pwkr, *pwvr, *pwor;
    cudaGetSymbolAddress((void**)&pq,  g_q);
    cudaGetSymbolAddress((void**)&pk,  g_k);
    cudaGetSymbolAddress((void**)&pv,  g_v);
    cudaGetSymbolAddress((void**)&pgk, g_gk);
    cudaGetSymbolAddress((void**)&pr1, g_r1);
    cudaGetSymbolAddress((void**)&pr2, g_r2);
    cudaGetSymbolAddress((void**)&pg,  g_g);
    cudaGetSymbolAddress((void**)&po,  g_o);
    cudaGetSymbolAddress((void**)&phsr, g_hsr);
    cudaGetSymbolAddress((void**)&pwqr, g_wqr);
    cudaGetSymbolAddress((void**)&pwkr, g_wkr);
    cudaGetSymbolAddress((void**)&pwvr, g_wvr);
    cudaGetSymbolAddress((void**)&pwor, g_wor);

    cudaFuncSetAttribute(tf32gemm4_kernel<true>,  cudaFuncAttributeMaxDynamicSharedMemorySize, PSM_BYTES);
    cudaFuncSetAttribute(tf32gemm4_kernel<false>, cudaFuncAttributeMaxDynamicSharedMemorySize, PSM_BYTES);
    cudaFuncSetAttribute(gla_kernel, cudaFuncAttributeMaxDynamicSharedMemorySize, SM_BYTES);

    // round+permute hs
    round_perm_kernel<<<(MM*DD/4 + 255)/256, 256>>>(hs, phsr, MM*DD/4, DD);
    // transpose+round+permute weights -> [N][K]
    {
        dim3 blk(32, 8);
        transpose_perm_kernel<<<dim3(NQK/32, DD/32), blk>>>(Wq, pwqr, DD, NQK);
        transpose_perm_kernel<<<dim3(NQK/32, DD/32), blk>>>(Wk, pwkr, DD, NQK);
        transpose_perm_kernel<<<dim3(NV/32,  DD/32), blk>>>(Wv, pwvr, DD, NV);
        transpose_perm_kernel<<<dim3(DD/32,  NV/32), blk>>>(Wo, pwor, NV, DD);
    }
    // projections with silu
    {
        dim3 grid(NQK / 256, MM / 128);
        tf32gemm4_kernel<true><<<grid, 512, PSM_BYTES>>>(phsr, pwqr, pq, MM, NQK, DD);
        tf32gemm4_kernel<true><<<grid, 512, PSM_BYTES>>>(phsr, pwkr, pk, MM, NQK, DD);
    }
    {
        dim3 grid(NV / 256, MM / 128);
        tf32gemm4_kernel<true><<<grid, 512, PSM_BYTES>>>(phsr, pwvr, pv, MM, NV, DD);
    }
    // fused low-rank stage 1 (hs read once), then stage 2 per gate
    lowrank1_fused_kernel<<<MM / 8, 256>>>(hs, Wgk1, Wg1, pr1, pr2, DD);
    lowrank2_kernel<<<(MM * NQK) / 256, 256>>>(pr1, Wgk2, bgk2, pgk, NQK, 1);
    lowrank2_kernel<<<(MM * NV) / 256, 256>>>(pr2, Wg2, bg2, pg, NV, 0);

    // chunked GLA (512 threads)
    gla_kernel<<<BB * HH * 4, 512, SM_BYTES>>>(pq, pk, pv, pgk, po);

    // rms norm + gate (writes permuted tf32 layout for the Wo GEMM)
    rmsgate_kernel<<<(MM * HH) / 8, 256>>>(po, pg, gnw);

    // output projection
    {
        dim3 grid(DD / 256, MM / 128);
        tf32gemm4_kernel<false><<<grid, 512, PSM_BYTES>>>(po, pwor, out, MM, DD, NV);
    }
    (void)in_sizes; (void)n_in; (void)out_size;
}